// round 14
// baseline (speedup 1.0000x reference)
#include <cuda_runtime.h>
#include <cuda_bf16.h>
#include <cstdint>

// Problem: B=4096, D=128, H=512
//   z = y @ W1 + t*v1 + b1 ; h = tanh(z) ; dy = h @ W2 + b2
//   div[b] = sum_k (1 - h[b,k]^2) * c_k,  c_k = sum_i W1[i,k]*W2[k,i]
// Output: dy (B*D floats) then -div (B floats).
// mma m16n8k16 bf16, 3-term split, fp32 acc. BM=32 (m-replication), 512 thr /
// 16 warps, grid=128. cp.async warp-private ring, 4 slots deep (~300cyc cover).

#define B_ 4096
#define D_ 128
#define H_ 512
#define BM 32
#define SU 68    // y smem row stride in uint32 (272B), mod 32 = 4
#define HSU 260  // h smem row stride in uint32 (1040B), mod 32 = 4

#define RING_WORDS 16384            // 16 warps x 256 uint4 (4KB/warp) = 64KB
#define YH_OFF RING_WORDS
#define YL_OFF (YH_OFF + BM * SU)
#define HH_OFF (YL_OFF + BM * SU)
#define HL_OFF (HH_OFF + BM * HSU)
#define SMEM_WORDS (HL_OFF + BM * HSU)
#define SMEM_BYTES (SMEM_WORDS * 4)

__device__ float g_c[H_];
__device__ float g_tb[H_];
__device__ uint4 g_W1p[512 * 32];   // kt<8 (D/16), nt<64 (H/8)
__device__ uint4 g_W2p[512 * 32];   // kt<32 (H/16), nt<16 (D/8)

#define CP16(dst, src) asm volatile("cp.async.cg.shared.global [%0], [%1], 16;" :: "r"(dst), "l"(src))
#define CPCOMMIT() asm volatile("cp.async.commit_group;")
#define CPWAIT(n)  asm volatile("cp.async.wait_group %0;" :: "n"(n))

__device__ __forceinline__ void split2(float a, float b, uint32_t& hi, uint32_t& lo) {
    __nv_bfloat16 ah = __float2bfloat16_rn(a);
    __nv_bfloat16 bh = __float2bfloat16_rn(b);
    __nv_bfloat16 al = __float2bfloat16_rn(a - __bfloat162float(ah));
    __nv_bfloat16 bl = __float2bfloat16_rn(b - __bfloat162float(bh));
    __nv_bfloat162 hp = __halves2bfloat162(ah, bh);
    __nv_bfloat162 lp = __halves2bfloat162(al, bl);
    hi = *reinterpret_cast<uint32_t*>(&hp);
    lo = *reinterpret_cast<uint32_t*>(&lp);
}

__device__ __forceinline__ void mma_bf16(float c[4], const uint32_t a[4],
                                         uint32_t b0, uint32_t b1) {
    asm volatile(
        "mma.sync.aligned.m16n8k16.row.col.f32.bf16.bf16.f32 "
        "{%0,%1,%2,%3}, {%4,%5,%6,%7}, {%8,%9}, {%0,%1,%2,%3};\n"
        : "+f"(c[0]), "+f"(c[1]), "+f"(c[2]), "+f"(c[3])
        : "r"(a[0]), "r"(a[1]), "r"(a[2]), "r"(a[3]), "r"(b0), "r"(b1));
}

__device__ __forceinline__ void ldsm4(uint32_t r[4], uint32_t addr) {
    asm volatile("ldmatrix.sync.aligned.m8n8.x4.shared.b16 {%0,%1,%2,%3}, [%4];"
                 : "=r"(r[0]), "=r"(r[1]), "=r"(r[2]), "=r"(r[3]) : "r"(addr));
}

// Fused setup: blocks 0..511 pack weight fragments; blocks 512..1023 compute c_k/tb_k.
__global__ __launch_bounds__(256) void setup_kernel(
    const float* __restrict__ t,  const float* __restrict__ W1,
    const float* __restrict__ b1, const float* __restrict__ v1,
    const float* __restrict__ W2) {
    __shared__ float red[4];
    if (blockIdx.x < 512) {
        int idx  = blockIdx.x * 256 + threadIdx.x;
        int comp = idx & 3;
        int lane = (idx >> 2) & 31;
        int frag = idx >> 7;
        int tig = lane & 3, gid = lane >> 2;
        int reg = comp & 1;
        bool ishi = comp < 2;
        float a, b;
        if (frag < 512) {  // W1
            int kt = frag >> 6, nt = frag & 63;
            int k0 = kt * 16 + 2 * tig + reg * 8;
            int n  = nt * 8 + gid;
            a = W1[(size_t)k0 * H_ + n];
            b = W1[(size_t)(k0 + 1) * H_ + n];
            uint32_t hi, lo; split2(a, b, hi, lo);
            ((uint32_t*)g_W1p)[frag * 128 + lane * 4 + comp] = ishi ? hi : lo;
        } else {           // W2
            int f2 = frag - 512;
            int kt = f2 >> 4, nt = f2 & 15;
            int k0 = kt * 16 + 2 * tig + reg * 8;
            int n  = nt * 8 + gid;
            a = W2[(size_t)k0 * D_ + n];
            b = W2[(size_t)(k0 + 1) * D_ + n];
            uint32_t hi, lo; split2(a, b, hi, lo);
            ((uint32_t*)g_W2p)[f2 * 128 + lane * 4 + comp] = ishi ? hi : lo;
        }
    } else {
        const int k = blockIdx.x - 512;
        const int i = threadIdx.x;
        if (i < 128) {
            float s = W1[(size_t)i * H_ + k] * W2[(size_t)k * D_ + i];
            #pragma unroll
            for (int off = 16; off > 0; off >>= 1)
                s += __shfl_xor_sync(0xFFFFFFFFu, s, off);
            if ((i & 31) == 0) red[i >> 5] = s;
        }
        __syncthreads();
        if (i == 0) {
            g_c[k]  = red[0] + red[1] + red[2] + red[3];
            g_tb[k] = b1[k] + t[0] * v1[k];
        }
    }
}

__global__ __launch_bounds__(512, 1) void ode_kernel(
    const float* __restrict__ y,
    const float* __restrict__ b2,
    float* __restrict__ out)
{
    extern __shared__ __align__(16) uint32_t dsm[];
    uint32_t* yh = dsm + YH_OFF;
    uint32_t* yl = dsm + YL_OFF;
    uint32_t* hh = dsm + HH_OFF;
    uint32_t* hl = dsm + HL_OFF;
    const uint4* ring = (const uint4*)dsm;

    const int tid  = threadIdx.x;
    const int warp = tid >> 5;      // 0..15
    const int lane = tid & 31;
    const int gid  = lane >> 2;
    const int tig  = lane & 3;
    const int mb   = blockIdx.x * BM;

    const uint32_t ring_s = (uint32_t)__cvta_generic_to_shared(dsm);
    const int wb4      = warp * 256;             // uint4 index of warp region
    const uint32_t wbB = ring_s + warp * 256 * 16;

    // ---- Phase A ring prologue: half-stages 0,1,2 (4-slot ring) ----
    #pragma unroll
    for (int hs = 0; hs < 3; hs++) {
        int kt = hs >> 1, hp = hs & 1;
        #pragma unroll
        for (int f = 0; f < 2; f++) {
            int ch = hp * 2 + f;
            const uint4* src = &g_W1p[(kt * 64 + ch * 16 + warp) * 32 + lane];
            uint32_t dst = wbB + ((hs * 2 + f) * 32 + lane) * 16;
            CP16(dst, src);
        }
        CPCOMMIT();
    }

    // Load + bf16-split y tile (32 x 128): two float4 per thread
    #pragma unroll
    for (int it = 0; it < 2; it++) {
        int i = tid + it * 512;
        int r = i >> 5, c4 = (i & 31) * 4;
        float4 v = *(const float4*)(y + (size_t)(mb + r) * D_ + c4);
        uint32_t h0, l0, h1, l1;
        split2(v.x, v.y, h0, l0);
        split2(v.z, v.w, h1, l1);
        int c = r * SU + (c4 >> 1);
        yh[c] = h0; yh[c + 1] = h1;
        yl[c] = l0; yl[c + 1] = l1;
    }
    __syncthreads();

    const int lrow = (lane & 7) + ((lane >> 3) & 1) * 8;
    const int lkof = (lane >> 4) * 16;
    const uint32_t yh_a = (uint32_t)__cvta_generic_to_shared(yh) + lrow * (SU * 4) + lkof;
    const uint32_t yl_a = (uint32_t)__cvta_generic_to_shared(yl) + lrow * (SU * 4) + lkof;
    const uint32_t hh_a = (uint32_t)__cvta_generic_to_shared(hh) + lrow * (HSU * 4) + lkof;
    const uint32_t hl_a = (uint32_t)__cvta_generic_to_shared(hl) + lrow * (HSU * 4) + lkof;
    const uint32_t MY = 16 * (SU * 4);    // second m-tile offset (y)
    const uint32_t MH = 16 * (HSU * 4);   // second m-tile offset (h)

    // ---- Phase A: z = y @ W1; warp owns 8 n-cols per ch, 32 m-rows ----
    float z[4][2][4] = {};   // [ch][mt][4]
    uint32_t ah0[4], al0[4], ah1[4], al1[4];
    #pragma unroll
    for (int hs = 0; hs < 16; hs++) {
        CPWAIT(2);
        int kt = hs >> 1, hp = hs & 1;
        if (hp == 0) {
            ldsm4(ah0, yh_a + kt * 32);
            ldsm4(al0, yl_a + kt * 32);
            ldsm4(ah1, yh_a + MY + kt * 32);
            ldsm4(al1, yl_a + MY + kt * 32);
        }
        #pragma unroll
        for (int f = 0; f < 2; f++) {
            int ch = hp * 2 + f;
            uint4 w = ring[wb4 + ((hs & 3) * 2 + f) * 32 + lane];
            mma_bf16(z[ch][0], ah0, w.x, w.y);
            mma_bf16(z[ch][1], ah1, w.x, w.y);
            mma_bf16(z[ch][0], ah0, w.z, w.w);
            mma_bf16(z[ch][1], ah1, w.z, w.w);
            mma_bf16(z[ch][0], al0, w.x, w.y);
            mma_bf16(z[ch][1], al1, w.x, w.y);
        }
        int nhs = hs + 3;
        if (nhs < 16) {
            int kt2 = nhs >> 1, hp2 = nhs & 1;
            #pragma unroll
            for (int f = 0; f < 2; f++) {
                int ch = hp2 * 2 + f;
                const uint4* src = &g_W1p[(kt2 * 64 + ch * 16 + warp) * 32 + lane];
                uint32_t dst = wbB + (((nhs & 3) * 2 + f) * 32 + lane) * 16;
                CP16(dst, src);
            }
        }
        CPCOMMIT();
    }

    // ---- tanh + divergence + bf16-split h into smem ----
    float dv[4] = {0.f, 0.f, 0.f, 0.f};
    #pragma unroll
    for (int ch = 0; ch < 4; ch++) {
        int gc = ch * 128 + warp * 8 + tig * 2;
        float tb0 = g_tb[gc], tb1 = g_tb[gc + 1];
        float cc0 = g_c[gc],  cc1 = g_c[gc + 1];
        #pragma unroll
        for (int mt = 0; mt < 2; mt++) {
            float h00 = tanhf(z[ch][mt][0] + tb0);
            float h01 = tanhf(z[ch][mt][1] + tb1);
            float h10 = tanhf(z[ch][mt][2] + tb0);
            float h11 = tanhf(z[ch][mt][3] + tb1);
            dv[mt * 2]     += cc0 * (1.f - h00 * h00) + cc1 * (1.f - h01 * h01);
            dv[mt * 2 + 1] += cc0 * (1.f - h10 * h10) + cc1 * (1.f - h11 * h11);
            uint32_t ph, pl;
            split2(h00, h01, ph, pl);
            hh[(gid + mt * 16) * HSU + (gc >> 1)] = ph;
            hl[(gid + mt * 16) * HSU + (gc >> 1)] = pl;
            split2(h10, h11, ph, pl);
            hh[(gid + 8 + mt * 16) * HSU + (gc >> 1)] = ph;
            hl[(gid + 8 + mt * 16) * HSU + (gc >> 1)] = pl;
        }
    }

    // ---- Phase B ring prologue: slots 0..2 (overlaps the sync) ----
    const int kg = warp >> 3;   // k-half
    const int wn = warp & 7;    // n-group (16 D-cols)
    #pragma unroll
    for (int s = 0; s < 3; s++) {
        #pragma unroll
        for (int nt = 0; nt < 2; nt++) {
            const uint4* src = &g_W2p[((kg * 16 + s) * 16 + wn * 2 + nt) * 32 + lane];
            uint32_t dst = wbB + ((s * 2 + nt) * 32 + lane) * 16;
            CP16(dst, src);
        }
        CPCOMMIT();
    }
    __syncthreads();

    // ---- Phase B: partial dy over this warp's 256 k, 16 D-cols, 32 m-rows ----
    float acc[2][2][4] = {};   // [mt][nt][4]
    #pragma unroll
    for (int i = 0; i < 16; i++) {
        CPWAIT(2);
        int ktg = kg * 16 + i;
        ldsm4(ah0, hh_a + ktg * 32);
        ldsm4(al0, hl_a + ktg * 32);
        ldsm4(ah1, hh_a + MH + ktg * 32);
        ldsm4(al1, hl_a + MH + ktg * 32);
        #pragma unroll
        for (int nt = 0; nt < 2; nt++) {
            uint4 w = ring[wb4 + ((i & 3) * 2 + nt) * 32 + lane];
            mma_bf16(acc[0][nt], ah0, w.x, w.y);
            mma_bf16(acc[1][nt], ah1, w.x, w.y);
            mma_bf16(acc[0][nt], ah0, w.z, w.w);
            mma_bf16(acc[1][nt], ah1, w.z, w.w);
            mma_bf16(acc[0][nt], al0, w.x, w.y);
            mma_bf16(acc[1][nt], al1, w.x, w.y);
        }
        int pi = i + 3;
        if (pi < 16) {
            #pragma unroll
            for (int nt = 0; nt < 2; nt++) {
                const uint4* src = &g_W2p[((kg * 16 + pi) * 16 + wn * 2 + nt) * 32 + lane];
                uint32_t dst = wbB + (((pi & 3) * 2 + nt) * 32 + lane) * 16;
                CP16(dst, src);
            }
        }
        CPCOMMIT();
    }

    // ---- Cross-k-half reduction (kg=1 -> smem, kg=0 adds) ----
    float* redbuf = (float*)(dsm + YH_OFF);   // y region dead after phase A
    if (kg == 1) {
        #pragma unroll
        for (int mt = 0; mt < 2; mt++)
            #pragma unroll
            for (int nt = 0; nt < 2; nt++)
                #pragma unroll
                for (int c = 0; c < 4; c++)
                    redbuf[(((wn * 4 + mt * 2 + nt) * 4) + c) * 32 + lane] = acc[mt][nt][c];
    }
    __syncthreads();

    if (kg == 0) {
        #pragma unroll
        for (int mt = 0; mt < 2; mt++) {
            #pragma unroll
            for (int nt = 0; nt < 2; nt++) {
                #pragma unroll
                for (int c = 0; c < 4; c++)
                    acc[mt][nt][c] += redbuf[(((wn * 4 + mt * 2 + nt) * 4) + c) * 32 + lane];
                int col = wn * 16 + nt * 8 + tig * 2;
                float b20 = b2[col], b21 = b2[col + 1];
                float2 o0 = make_float2(acc[mt][nt][0] + b20, acc[mt][nt][1] + b21);
                float2 o1 = make_float2(acc[mt][nt][2] + b20, acc[mt][nt][3] + b21);
                *(float2*)(out + (size_t)(mb + gid + mt * 16) * D_ + col)     = o0;
                *(float2*)(out + (size_t)(mb + gid + 8 + mt * 16) * D_ + col) = o1;
            }
        }
    }

    // ---- Divergence reduce: over tig, then 16 warps ----
    #pragma unroll
    for (int j = 0; j < 4; j++) {
        dv[j] += __shfl_xor_sync(0xFFFFFFFFu, dv[j], 1);
        dv[j] += __shfl_xor_sync(0xFFFFFFFFu, dv[j], 2);
    }
    float* sdv = (float*)(dsm + HH_OFF);      // h region dead after phase B
    if (tig == 0) {
        sdv[gid * 16 + warp]        = dv[0];
        sdv[(gid + 8) * 16 + warp]  = dv[1];
        sdv[(gid + 16) * 16 + warp] = dv[2];
        sdv[(gid + 24) * 16 + warp] = dv[3];
    }
    __syncthreads();
    if (tid < BM) {
        float s = 0.f;
        #pragma unroll
        for (int w = 0; w < 16; w++) s += sdv[tid * 16 + w];
        out[(size_t)B_ * D_ + mb + tid] = -s;
    }
}

extern "C" void kernel_launch(void* const* d_in, const int* in_sizes, int n_in,
                              void* d_out, int out_size) {
    // Input order: t, y, logp, W1, b1, v1, W2, b2
    const float* t  = (const float*)d_in[0];
    const float* y  = (const float*)d_in[1];
    const float* W1 = (const float*)d_in[3];
    const float* b1 = (const float*)d_in[4];
    const float* v1 = (const float*)d_in[5];
    const float* W2 = (const float*)d_in[6];
    const float* b2 = (const float*)d_in[7];
    float* out = (float*)d_out;

    static bool attr_set = false;
    if (!attr_set) {
        cudaFuncSetAttribute(ode_kernel, cudaFuncAttributeMaxDynamicSharedMemorySize,
                             SMEM_BYTES);
        attr_set = true;
    }

    setup_kernel<<<1024, 256>>>(t, W1, b1, v1, W2);
    ode_kernel<<<B_ / BM, 512, SMEM_BYTES>>>(y, b2, out);
}

// round 15
// speedup vs baseline: 1.0691x; 1.0691x over previous
#include <cuda_runtime.h>
#include <cuda_bf16.h>
#include <cstdint>

// Problem: B=4096, D=128, H=512
//   z = y @ W1 + t*v1 + b1 ; h = tanh(z) ; dy = h @ W2 + b2
//   div[b] = sum_k (1 - h[b,k]^2) * c_k,  c_k = sum_i W1[i,k]*W2[k,i]
// Output: dy (B*D floats) then -div (B floats).
// mma m16n8k16 bf16, 3-term split, fp32 acc. BM=32 (m-replication), 512 thr /
// 16 warps, grid=128. Weight fragments loaded DIRECTLY via LDG.128 (no ring).

#define B_ 4096
#define D_ 128
#define H_ 512
#define BM 32
#define SU 68    // y smem row stride in uint32 (272B), mod 32 = 4
#define HSU 260  // h smem row stride in uint32 (1040B), mod 32 = 4

#define YH_OFF 0
#define YL_OFF (YH_OFF + BM * SU)
#define HH_OFF (YL_OFF + BM * SU)
#define HL_OFF (HH_OFF + BM * HSU)
#define SMEM_WORDS (HL_OFF + BM * HSU)
#define SMEM_BYTES (SMEM_WORDS * 4)

__device__ float g_c[H_];
__device__ float g_tb[H_];
__device__ uint4 g_W1p[512 * 32];   // kt<8 (D/16), nt<64 (H/8)
__device__ uint4 g_W2p[512 * 32];   // kt<32 (H/16), nt<16 (D/8)

__device__ __forceinline__ void split2(float a, float b, uint32_t& hi, uint32_t& lo) {
    __nv_bfloat16 ah = __float2bfloat16_rn(a);
    __nv_bfloat16 bh = __float2bfloat16_rn(b);
    __nv_bfloat16 al = __float2bfloat16_rn(a - __bfloat162float(ah));
    __nv_bfloat16 bl = __float2bfloat16_rn(b - __bfloat162float(bh));
    __nv_bfloat162 hp = __halves2bfloat162(ah, bh);
    __nv_bfloat162 lp = __halves2bfloat162(al, bl);
    hi = *reinterpret_cast<uint32_t*>(&hp);
    lo = *reinterpret_cast<uint32_t*>(&lp);
}

__device__ __forceinline__ void mma_bf16(float c[4], const uint32_t a[4],
                                         uint32_t b0, uint32_t b1) {
    asm volatile(
        "mma.sync.aligned.m16n8k16.row.col.f32.bf16.bf16.f32 "
        "{%0,%1,%2,%3}, {%4,%5,%6,%7}, {%8,%9}, {%0,%1,%2,%3};\n"
        : "+f"(c[0]), "+f"(c[1]), "+f"(c[2]), "+f"(c[3])
        : "r"(a[0]), "r"(a[1]), "r"(a[2]), "r"(a[3]), "r"(b0), "r"(b1));
}

__device__ __forceinline__ void ldsm4(uint32_t r[4], uint32_t addr) {
    asm volatile("ldmatrix.sync.aligned.m8n8.x4.shared.b16 {%0,%1,%2,%3}, [%4];"
                 : "=r"(r[0]), "=r"(r[1]), "=r"(r[2]), "=r"(r[3]) : "r"(addr));
}

// Fused setup: blocks 0..511 pack weight fragments; blocks 512..1023 compute c_k/tb_k.
__global__ __launch_bounds__(256) void setup_kernel(
    const float* __restrict__ t,  const float* __restrict__ W1,
    const float* __restrict__ b1, const float* __restrict__ v1,
    const float* __restrict__ W2) {
    __shared__ float red[4];
    if (blockIdx.x < 512) {
        int idx  = blockIdx.x * 256 + threadIdx.x;
        int comp = idx & 3;
        int lane = (idx >> 2) & 31;
        int frag = idx >> 7;
        int tig = lane & 3, gid = lane >> 2;
        int reg = comp & 1;
        bool ishi = comp < 2;
        float a, b;
        if (frag < 512) {  // W1
            int kt = frag >> 6, nt = frag & 63;
            int k0 = kt * 16 + 2 * tig + reg * 8;
            int n  = nt * 8 + gid;
            a = W1[(size_t)k0 * H_ + n];
            b = W1[(size_t)(k0 + 1) * H_ + n];
            uint32_t hi, lo; split2(a, b, hi, lo);
            ((uint32_t*)g_W1p)[frag * 128 + lane * 4 + comp] = ishi ? hi : lo;
        } else {           // W2
            int f2 = frag - 512;
            int kt = f2 >> 4, nt = f2 & 15;
            int k0 = kt * 16 + 2 * tig + reg * 8;
            int n  = nt * 8 + gid;
            a = W2[(size_t)k0 * D_ + n];
            b = W2[(size_t)(k0 + 1) * D_ + n];
            uint32_t hi, lo; split2(a, b, hi, lo);
            ((uint32_t*)g_W2p)[f2 * 128 + lane * 4 + comp] = ishi ? hi : lo;
        }
    } else {
        const int k = blockIdx.x - 512;
        const int i = threadIdx.x;
        if (i < 128) {
            float s = W1[(size_t)i * H_ + k] * W2[(size_t)k * D_ + i];
            #pragma unroll
            for (int off = 16; off > 0; off >>= 1)
                s += __shfl_xor_sync(0xFFFFFFFFu, s, off);
            if ((i & 31) == 0) red[i >> 5] = s;
        }
        __syncthreads();
        if (i == 0) {
            g_c[k]  = red[0] + red[1] + red[2] + red[3];
            g_tb[k] = b1[k] + t[0] * v1[k];
        }
    }
}

__global__ __launch_bounds__(512, 1) void ode_kernel(
    const float* __restrict__ y,
    const float* __restrict__ b2,
    float* __restrict__ out)
{
    extern __shared__ __align__(16) uint32_t dsm[];
    uint32_t* yh = dsm + YH_OFF;
    uint32_t* yl = dsm + YL_OFF;
    uint32_t* hh = dsm + HH_OFF;
    uint32_t* hl = dsm + HL_OFF;

    const int tid  = threadIdx.x;
    const int warp = tid >> 5;      // 0..15
    const int lane = tid & 31;
    const int gid  = lane >> 2;
    const int tig  = lane & 3;
    const int mb   = blockIdx.x * BM;

    // Load + bf16-split y tile (32 x 128): two float4 per thread
    #pragma unroll
    for (int it = 0; it < 2; it++) {
        int i = tid + it * 512;
        int r = i >> 5, c4 = (i & 31) * 4;
        float4 v = *(const float4*)(y + (size_t)(mb + r) * D_ + c4);
        uint32_t h0, l0, h1, l1;
        split2(v.x, v.y, h0, l0);
        split2(v.z, v.w, h1, l1);
        int c = r * SU + (c4 >> 1);
        yh[c] = h0; yh[c + 1] = h1;
        yl[c] = l0; yl[c + 1] = l1;
    }
    __syncthreads();

    const int lrow = (lane & 7) + ((lane >> 3) & 1) * 8;
    const int lkof = (lane >> 4) * 16;
    const uint32_t yh_a = (uint32_t)__cvta_generic_to_shared(yh) + lrow * (SU * 4) + lkof;
    const uint32_t yl_a = (uint32_t)__cvta_generic_to_shared(yl) + lrow * (SU * 4) + lkof;
    const uint32_t hh_a = (uint32_t)__cvta_generic_to_shared(hh) + lrow * (HSU * 4) + lkof;
    const uint32_t hl_a = (uint32_t)__cvta_generic_to_shared(hl) + lrow * (HSU * 4) + lkof;
    const uint32_t MY = 16 * (SU * 4);    // second m-tile offset (y)
    const uint32_t MH = 16 * (HSU * 4);   // second m-tile offset (h)

    // ---- Phase A: z = y @ W1; warp owns 8 n-cols per ch, 32 m-rows ----
    float z[4][2][4] = {};   // [ch][mt][4]
    uint32_t ah0[4], al0[4], ah1[4], al1[4];
    #pragma unroll
    for (int kt = 0; kt < 8; kt++) {
        // Prefetch this kt's 4 weight fragments up front (MLP across LDG.128)
        uint4 w0 = g_W1p[(kt * 64 + 0 * 16 + warp) * 32 + lane];
        uint4 w1 = g_W1p[(kt * 64 + 1 * 16 + warp) * 32 + lane];
        uint4 w2 = g_W1p[(kt * 64 + 2 * 16 + warp) * 32 + lane];
        uint4 w3 = g_W1p[(kt * 64 + 3 * 16 + warp) * 32 + lane];
        ldsm4(ah0, yh_a + kt * 32);
        ldsm4(al0, yl_a + kt * 32);
        ldsm4(ah1, yh_a + MY + kt * 32);
        ldsm4(al1, yl_a + MY + kt * 32);
        mma_bf16(z[0][0], ah0, w0.x, w0.y);
        mma_bf16(z[0][1], ah1, w0.x, w0.y);
        mma_bf16(z[0][0], ah0, w0.z, w0.w);
        mma_bf16(z[0][1], ah1, w0.z, w0.w);
        mma_bf16(z[0][0], al0, w0.x, w0.y);
        mma_bf16(z[0][1], al1, w0.x, w0.y);
        mma_bf16(z[1][0], ah0, w1.x, w1.y);
        mma_bf16(z[1][1], ah1, w1.x, w1.y);
        mma_bf16(z[1][0], ah0, w1.z, w1.w);
        mma_bf16(z[1][1], ah1, w1.z, w1.w);
        mma_bf16(z[1][0], al0, w1.x, w1.y);
        mma_bf16(z[1][1], al1, w1.x, w1.y);
        mma_bf16(z[2][0], ah0, w2.x, w2.y);
        mma_bf16(z[2][1], ah1, w2.x, w2.y);
        mma_bf16(z[2][0], ah0, w2.z, w2.w);
        mma_bf16(z[2][1], ah1, w2.z, w2.w);
        mma_bf16(z[2][0], al0, w2.x, w2.y);
        mma_bf16(z[2][1], al1, w2.x, w2.y);
        mma_bf16(z[3][0], ah0, w3.x, w3.y);
        mma_bf16(z[3][1], ah1, w3.x, w3.y);
        mma_bf16(z[3][0], ah0, w3.z, w3.w);
        mma_bf16(z[3][1], ah1, w3.z, w3.w);
        mma_bf16(z[3][0], al0, w3.x, w3.y);
        mma_bf16(z[3][1], al1, w3.x, w3.y);
    }

    // ---- tanh + divergence + bf16-split h into smem ----
    float dv[4] = {0.f, 0.f, 0.f, 0.f};
    #pragma unroll
    for (int ch = 0; ch < 4; ch++) {
        int gc = ch * 128 + warp * 8 + tig * 2;
        float tb0 = g_tb[gc], tb1 = g_tb[gc + 1];
        float cc0 = g_c[gc],  cc1 = g_c[gc + 1];
        #pragma unroll
        for (int mt = 0; mt < 2; mt++) {
            float h00 = tanhf(z[ch][mt][0] + tb0);
            float h01 = tanhf(z[ch][mt][1] + tb1);
            float h10 = tanhf(z[ch][mt][2] + tb0);
            float h11 = tanhf(z[ch][mt][3] + tb1);
            dv[mt * 2]     += cc0 * (1.f - h00 * h00) + cc1 * (1.f - h01 * h01);
            dv[mt * 2 + 1] += cc0 * (1.f - h10 * h10) + cc1 * (1.f - h11 * h11);
            uint32_t ph, pl;
            split2(h00, h01, ph, pl);
            hh[(gid + mt * 16) * HSU + (gc >> 1)] = ph;
            hl[(gid + mt * 16) * HSU + (gc >> 1)] = pl;
            split2(h10, h11, ph, pl);
            hh[(gid + 8 + mt * 16) * HSU + (gc >> 1)] = ph;
            hl[(gid + 8 + mt * 16) * HSU + (gc >> 1)] = pl;
        }
    }
    __syncthreads();

    // ---- Phase B: partial dy over this warp's 256 k, 16 D-cols, 32 m-rows ----
    const int kg = warp >> 3;   // k-half
    const int wn = warp & 7;    // n-group (16 D-cols)
    float acc[2][2][4] = {};    // [mt][nt][4]
    #pragma unroll
    for (int i = 0; i < 16; i++) {
        int ktg = kg * 16 + i;
        uint4 w0 = g_W2p[(ktg * 16 + wn * 2 + 0) * 32 + lane];
        uint4 w1 = g_W2p[(ktg * 16 + wn * 2 + 1) * 32 + lane];
        ldsm4(ah0, hh_a + ktg * 32);
        ldsm4(al0, hl_a + ktg * 32);
        ldsm4(ah1, hh_a + MH + ktg * 32);
        ldsm4(al1, hl_a + MH + ktg * 32);
        mma_bf16(acc[0][0], ah0, w0.x, w0.y);
        mma_bf16(acc[1][0], ah1, w0.x, w0.y);
        mma_bf16(acc[0][0], ah0, w0.z, w0.w);
        mma_bf16(acc[1][0], ah1, w0.z, w0.w);
        mma_bf16(acc[0][0], al0, w0.x, w0.y);
        mma_bf16(acc[1][0], al1, w0.x, w0.y);
        mma_bf16(acc[0][1], ah0, w1.x, w1.y);
        mma_bf16(acc[1][1], ah1, w1.x, w1.y);
        mma_bf16(acc[0][1], ah0, w1.z, w1.w);
        mma_bf16(acc[1][1], ah1, w1.z, w1.w);
        mma_bf16(acc[0][1], al0, w1.x, w1.y);
        mma_bf16(acc[1][1], al1, w1.x, w1.y);
    }

    // ---- Cross-k-half reduction (kg=1 -> smem, kg=0 adds) ----
    float* redbuf = (float*)(dsm + YH_OFF);   // y region dead after phase A
    if (kg == 1) {
        #pragma unroll
        for (int mt = 0; mt < 2; mt++)
            #pragma unroll
            for (int nt = 0; nt < 2; nt++)
                #pragma unroll
                for (int c = 0; c < 4; c++)
                    redbuf[(((wn * 4 + mt * 2 + nt) * 4) + c) * 32 + lane] = acc[mt][nt][c];
    }
    __syncthreads();

    if (kg == 0) {
        #pragma unroll
        for (int mt = 0; mt < 2; mt++) {
            #pragma unroll
            for (int nt = 0; nt < 2; nt++) {
                #pragma unroll
                for (int c = 0; c < 4; c++)
                    acc[mt][nt][c] += redbuf[(((wn * 4 + mt * 2 + nt) * 4) + c) * 32 + lane];
                int col = wn * 16 + nt * 8 + tig * 2;
                float b20 = b2[col], b21 = b2[col + 1];
                float2 o0 = make_float2(acc[mt][nt][0] + b20, acc[mt][nt][1] + b21);
                float2 o1 = make_float2(acc[mt][nt][2] + b20, acc[mt][nt][3] + b21);
                *(float2*)(out + (size_t)(mb + gid + mt * 16) * D_ + col)     = o0;
                *(float2*)(out + (size_t)(mb + gid + 8 + mt * 16) * D_ + col) = o1;
            }
        }
    }

    // ---- Divergence reduce: over tig, then 16 warps ----
    #pragma unroll
    for (int j = 0; j < 4; j++) {
        dv[j] += __shfl_xor_sync(0xFFFFFFFFu, dv[j], 1);
        dv[j] += __shfl_xor_sync(0xFFFFFFFFu, dv[j], 2);
    }
    float* sdv = (float*)(dsm + HH_OFF);      // h region dead after phase B
    if (tig == 0) {
        sdv[gid * 16 + warp]        = dv[0];
        sdv[(gid + 8) * 16 + warp]  = dv[1];
        sdv[(gid + 16) * 16 + warp] = dv[2];
        sdv[(gid + 24) * 16 + warp] = dv[3];
    }
    __syncthreads();
    if (tid < BM) {
        float s = 0.f;
        #pragma unroll
        for (int w = 0; w < 16; w++) s += sdv[tid * 16 + w];
        out[(size_t)B_ * D_ + mb + tid] = -s;
    }
}

extern "C" void kernel_launch(void* const* d_in, const int* in_sizes, int n_in,
                              void* d_out, int out_size) {
    // Input order: t, y, logp, W1, b1, v1, W2, b2
    const float* t  = (const float*)d_in[0];
    const float* y  = (const float*)d_in[1];
    const float* W1 = (const float*)d_in[3];
    const float* b1 = (const float*)d_in[4];
    const float* v1 = (const float*)d_in[5];
    const float* W2 = (const float*)d_in[6];
    const float* b2 = (const float*)d_in[7];
    float* out = (float*)d_out;

    static bool attr_set = false;
    if (!attr_set) {
        cudaFuncSetAttribute(ode_kernel, cudaFuncAttributeMaxDynamicSharedMemorySize,
                             SMEM_BYTES);
        attr_set = true;
    }

    setup_kernel<<<1024, 256>>>(t, W1, b1, v1, W2);
    ode_kernel<<<B_ / BM, 512, SMEM_BYTES>>>(y, b2, out);
}